// round 17
// baseline (speedup 1.0000x reference)
#include <cuda_runtime.h>

typedef unsigned long long u64;

#define NQ   14
#define DIM  (1 << NQ)       // 16384
#define NL   3
#define TPB  1024
#define UN   8               // SoA units per thread (16 amps)
#define SMEM_BYTES (DIM * sizeof(float2))   // 131072

// ---- packed f32x2 helpers ----
__device__ __forceinline__ u64 pack2(float lo, float hi) {
    u64 r; asm("mov.b64 %0, {%1,%2};" : "=l"(r) : "f"(lo), "f"(hi)); return r;
}
__device__ __forceinline__ void unpack2(u64 a, float& lo, float& hi) {
    asm("mov.b64 {%0,%1}, %2;" : "=f"(lo), "=f"(hi) : "l"(a));
}
__device__ __forceinline__ u64 blo(u64 a) {   // (lo,lo)
    u64 r; asm("{\n\t.reg .b32 l,h;\n\tmov.b64 {l,h}, %1;\n\tmov.b64 %0, {l,l};\n\t}"
               : "=l"(r) : "l"(a)); return r;
}
__device__ __forceinline__ u64 bhi(u64 a) {   // (hi,hi)
    u64 r; asm("{\n\t.reg .b32 l,h;\n\tmov.b64 {l,h}, %1;\n\tmov.b64 %0, {h,h};\n\t}"
               : "=l"(r) : "l"(a)); return r;
}
__device__ __forceinline__ u64 fma2(u64 a, u64 b, u64 c) {
    u64 d; asm("fma.rn.f32x2 %0, %1, %2, %3;" : "=l"(d) : "l"(a), "l"(b), "l"(c)); return d;
}
__device__ __forceinline__ u64 mul2(u64 a, u64 b) {
    u64 d; asm("mul.rn.f32x2 %0, %1, %2;" : "=l"(d) : "l"(a), "l"(b)); return d;
}

// Vectorized complex 2x2 butterfly on SoA-packed pair (two independent problems).
// g: [0]=(r00,r00) [1]=(-i00,-i00) [2]=(r01,r01) [3]=(-i01,-i01)
//    [4]=(i00,i00) [5]=(i01,i01)   [6]=(-r01,-r01)
// Rot structure: g11 = conj(g00), g10 = -conj(g01).
__device__ __forceinline__ void apply2v(const u64* g, u64& R0, u64& I0, u64& R1, u64& I1)
{
    u64 n0r = mul2(R0, g[0]); n0r = fma2(I0, g[1], n0r); n0r = fma2(R1, g[2], n0r); n0r = fma2(I1, g[3], n0r);
    u64 n0i = mul2(R0, g[4]); n0i = fma2(I0, g[0], n0i); n0i = fma2(R1, g[5], n0i); n0i = fma2(I1, g[2], n0i);
    u64 n1r = mul2(R0, g[6]); n1r = fma2(I0, g[3], n1r); n1r = fma2(R1, g[0], n1r); n1r = fma2(I1, g[4], n1r);
    u64 n1i = mul2(R0, g[5]); n1i = fma2(I0, g[6], n1i); n1i = fma2(R1, g[1], n1i); n1i = fma2(I1, g[0], n1i);
    R0 = n0r; I0 = n0i; R1 = n1r; I1 = n1i;
}

// bank-conflict-avoiding SMEM swizzle (pure relabeling; used on EVERY s[] access)
__device__ __forceinline__ unsigned swz(unsigned a) { return a ^ ((a >> 5) & 31u); }

__global__ __launch_bounds__(TPB, 1)
void qsim_kernel(const float* __restrict__ x,
                 const float* __restrict__ qw,
                 const float* __restrict__ wlin,
                 const float* __restrict__ blin,
                 float* __restrict__ out)
{
    extern __shared__ float2 s[];             // 128 KB scalar exchange buffer
    __shared__ u64      sg[NL * NQ][14];      // packed gate constants
    __shared__ unsigned sF[NL - 1][NQ];       // ring-map F columns for layers 1..NL-1
    __shared__ float    scS[NQ], scC[NQ];     // per-wire sin/cos of x/2
    __shared__ float    red[TPB / 32];

    const int t    = threadIdx.x;
    const int lane = t & 31;
    const int warp = t >> 5;
    const int b    = blockIdx.x;

    u64 R[UN], I[UN];                         // 16 amps, SoA packed over u bit 3

    // ---- cooperative precompute: gates, ring columns, embedding sincos ----
    if (t < NL * NQ) {
        float phi = qw[t * 3 + 0], th = qw[t * 3 + 1], om = qw[t * 3 + 2];
        float ct, st, ca, sa, cb, sb;
        sincosf(0.5f * th,         &st, &ct);
        sincosf(0.5f * (phi + om), &sa, &ca);
        sincosf(0.5f * (phi - om), &sb, &cb);
        float r00 =  ct * ca, i00 = -ct * sa;
        float r01 = -st * cb, i01 = -st * sb;
        sg[t][0]  = pack2(r00,  r00);
        sg[t][1]  = pack2(-i00, -i00);
        sg[t][2]  = pack2(r01,  r01);
        sg[t][3]  = pack2(-i01, -i01);
        sg[t][4]  = pack2(i00,  i00);
        sg[t][5]  = pack2(i01,  i01);
        sg[t][6]  = pack2(-r01, -r01);
        sg[t][7]  = 0;
        sg[t][8]  = pack2(r00, -r01);
        sg[t][9]  = pack2(-i00, -i01);
        sg[t][10] = pack2(r01,  r00);
        sg[t][11] = pack2(-i01, i00);
        sg[t][12] = pack2(i00,  i01);
        sg[t][13] = pack2(i01, -i00);
    } else if (t >= 128 && t < 128 + (NL - 1) * NQ) {
        // F column j for ring range rr: ops w=13..0 (descending build)
        int idx = t - 128;
        int rr  = idx / NQ + 1;
        int j   = idx % NQ;
        unsigned z = 1u << j;
        for (int w = NQ - 1; w >= 0; w--) {
            int bc = NQ - 1 - w;
            int bt = NQ - 1 - ((w + rr) % NQ);
            z ^= ((z >> bc) & 1u) << bt;
        }
        sF[rr - 1][j] = z;
    } else if (t >= 512 && t < 512 + NQ) {
        int w = t - 512;
        float sv, cv;
        sincosf(0.5f * x[b * NQ + w], &sv, &cv);
        scS[w] = sv; scC[w] = cv;
    }
    __syncthreads();

    // ---- init in registers: RX product state on |0..0> ----
    // Layout A: y = (t<<4)|u.  t bit j <-> y bit 4+j <-> wire 9-j;
    // u bits 0-2 <-> wires 13,12,11; u bit 3 <-> wire 10 (SoA slot bit).
    float tmag = 1.0f;
    #pragma unroll
    for (int j = 0; j < 10; j++)
        tmag *= ((t >> j) & 1) ? scS[9 - j] : scC[9 - j];
    const int tp = __popc((unsigned)t);
    #pragma unroll
    for (int k = 0; k < UN; k++) {
        float m = tmag;
        m *= (k & 1) ? scS[13] : scC[13];
        m *= (k & 2) ? scS[12] : scC[12];
        m *= (k & 4) ? scS[11] : scC[11];
        float m0 = m * scC[10];               // u bit3 = 0
        float m1 = m * scS[10];               // u bit3 = 1
        int k0 = (tp + __popc((unsigned)k)) & 3;
        int k1 = (k0 + 1) & 3;
        float re0 = (k0 == 0) ? m0 : ((k0 == 2) ? -m0 : 0.0f);
        float im0 = (k0 == 3) ? m0 : ((k0 == 1) ? -m0 : 0.0f);
        float re1 = (k1 == 0) ? m1 : ((k1 == 2) ? -m1 : 0.0f);
        float im1 = (k1 == 3) ? m1 : ((k1 == 1) ? -m1 : 0.0f);
        R[k] = pack2(re0, re1);
        I[k] = pack2(im0, im1);
    }

    for (int l = 0; l < NL; l++) {
        // ---- Phase A gather (layers 1,2): previous ring folded into addresses ----
        if (l > 0) {
            const unsigned* Fc = sF[l - 1];
            unsigned Fb = 0;
            #pragma unroll
            for (int j = 0; j < 10; j++)
                if ((t >> j) & 1) Fb ^= Fc[4 + j];
            const unsigned F3 = Fc[3];
            #pragma unroll
            for (int k = 0; k < UN; k++) {
                unsigned fy = Fb;
                if (k & 1) fy ^= Fc[0];
                if (k & 2) fy ^= Fc[1];
                if (k & 4) fy ^= Fc[2];
                float2 a = s[swz(fy)];
                float2 c = s[swz(fy ^ F3)];
                R[k] = pack2(a.x, c.x);
                I[k] = pack2(a.y, c.y);
            }
        }

        // ---- Phase A gates ----
        // wires 13,12,11 on u bits 0-2 (vectorized)
        #pragma unroll
        for (int q = 0; q < 3; q++) {
            const u64* g = sg[l * NQ + (13 - q)];
            #pragma unroll
            for (int k = 0; k < UN; k++)
                if (!(k & (1 << q)))
                    apply2v(g, R[k], I[k], R[k | (1 << q)], I[k | (1 << q)]);
        }
        // wire 10 on u bit 3 (vector bit): intra-register, mixed consts
        {
            const u64* g = sg[l * NQ + 10];
            #pragma unroll
            for (int k = 0; k < UN; k++) {
                u64 br0 = blo(R[k]), bi0 = blo(I[k]);
                u64 br1 = bhi(R[k]), bi1 = bhi(I[k]);
                u64 nr = mul2(br0, g[8]);  nr = fma2(bi0, g[9],  nr); nr = fma2(br1, g[10], nr); nr = fma2(bi1, g[11], nr);
                u64 ni = mul2(br0, g[12]); ni = fma2(bi0, g[8],  ni); ni = fma2(br1, g[13], ni); ni = fma2(bi1, g[10], ni);
                R[k] = nr; I[k] = ni;
            }
        }
        // wires 9-5 on lane bits 0-4 (vectorized, lane-selected consts)
        #pragma unroll
        for (int ql = 0; ql < 5; ql++) {
            const u64* g = sg[l * NQ + (9 - ql)];
            int bit = (lane >> ql) & 1;
            u64 Arr = g[0];
            u64 Ari = bit ? g[4] : g[1];
            u64 Air = bit ? g[1] : g[4];
            u64 Brr = bit ? g[6] : g[2];
            u64 Bri = g[3];
            u64 Bir = g[5];
            #pragma unroll
            for (int k = 0; k < UN; k++) {
                u64 oR = __shfl_xor_sync(0xffffffffu, R[k], 1 << ql);
                u64 oI = __shfl_xor_sync(0xffffffffu, I[k], 1 << ql);
                u64 nr = mul2(R[k], Arr); nr = fma2(I[k], Ari, nr); nr = fma2(oR, Brr, nr); nr = fma2(oI, Bri, nr);
                u64 ni = mul2(R[k], Air); ni = fma2(I[k], Arr, ni); ni = fma2(oR, Bir, ni); ni = fma2(oI, Brr, ni);
                R[k] = nr; I[k] = ni;
            }
        }

        __syncthreads();                      // all phase-A gathers done (cross-thread)
        #pragma unroll
        for (int k = 0; k < UN; k++) {        // store scalar layout A
            float r0, r1, i0, i1;
            unpack2(R[k], r0, r1); unpack2(I[k], i0, i1);
            unsigned y0 = ((unsigned)t << 4) | (unsigned)k;
            s[swz(y0)]     = make_float2(r0, i0);
            s[swz(y0 | 8)] = make_float2(r1, i1);
        }
        __syncthreads();                      // stores visible

        // ---- Phase B: y = warp | (lane<<5) | (u<<10); u bit3 = y bit13 = SoA slot ----
        #pragma unroll
        for (int k = 0; k < UN; k++) {
            unsigned y0 = (unsigned)warp | ((unsigned)lane << 5) | ((unsigned)k << 10);
            float2 a = s[swz(y0)];
            float2 c = s[swz(y0 | (1u << 13))];
            R[k] = pack2(a.x, c.x);
            I[k] = pack2(a.y, c.y);
        }
        // wires 3,2,1 on u bits 0-2 (vectorized)
        #pragma unroll
        for (int q = 0; q < 3; q++) {
            const u64* g = sg[l * NQ + (3 - q)];
            #pragma unroll
            for (int k = 0; k < UN; k++)
                if (!(k & (1 << q)))
                    apply2v(g, R[k], I[k], R[k | (1 << q)], I[k | (1 << q)]);
        }
        // wire 0 on u bit 3 (vector bit)
        {
            const u64* g = sg[l * NQ + 0];
            #pragma unroll
            for (int k = 0; k < UN; k++) {
                u64 br0 = blo(R[k]), bi0 = blo(I[k]);
                u64 br1 = bhi(R[k]), bi1 = bhi(I[k]);
                u64 nr = mul2(br0, g[8]);  nr = fma2(bi0, g[9],  nr); nr = fma2(br1, g[10], nr); nr = fma2(bi1, g[11], nr);
                u64 ni = mul2(br0, g[12]); ni = fma2(bi0, g[8],  ni); ni = fma2(br1, g[13], ni); ni = fma2(bi1, g[10], ni);
                R[k] = nr; I[k] = ni;
            }
        }
        // wire 4 on lane bit 4 (y bit 9): single shuffle sweep
        {
            const u64* g = sg[l * NQ + 4];
            int bit = (lane >> 4) & 1;
            u64 Arr = g[0];
            u64 Ari = bit ? g[4] : g[1];
            u64 Air = bit ? g[1] : g[4];
            u64 Brr = bit ? g[6] : g[2];
            u64 Bri = g[3];
            u64 Bir = g[5];
            #pragma unroll
            for (int k = 0; k < UN; k++) {
                u64 oR = __shfl_xor_sync(0xffffffffu, R[k], 16);
                u64 oI = __shfl_xor_sync(0xffffffffu, I[k], 16);
                u64 nr = mul2(R[k], Arr); nr = fma2(I[k], Ari, nr); nr = fma2(oR, Brr, nr); nr = fma2(oI, Bri, nr);
                u64 ni = mul2(R[k], Air); ni = fma2(I[k], Arr, ni); ni = fma2(oR, Bir, ni); ni = fma2(oI, Brr, ni);
                R[k] = nr; I[k] = ni;
            }
        }

        if (l < NL - 1) {
            // no barrier needed before these stores: each thread's B-store set
            // equals its own B-load set (private slots).
            #pragma unroll
            for (int k = 0; k < UN; k++) {
                float r0, r1, i0, i1;
                unpack2(R[k], r0, r1); unpack2(I[k], i0, i1);
                unsigned y0 = (unsigned)warp | ((unsigned)lane << 5) | ((unsigned)k << 10);
                s[swz(y0)]              = make_float2(r0, i0);
                s[swz(y0 | (1u << 13))] = make_float2(r1, i1);
            }
            __syncthreads();                  // stores visible for next A-gather
        }
    }

    // ---- last CNOT ring (r = NL) folded into expval signs (validated) ----
    unsigned Ar[NQ];
    #pragma unroll
    for (int i = 0; i < NQ; i++) Ar[i] = 1u << i;
    {
        const int rr = NL;
        #pragma unroll
        for (int w = 0; w < NQ; w++) {
            int bc = NQ - 1 - w;
            int bt = NQ - 1 - ((w + rr) % NQ);
            Ar[bt] ^= Ar[bc];
        }
    }
    float    wl[NQ];
    unsigned rf[NQ];
    #pragma unroll
    for (int w = 0; w < NQ; w++) { wl[w] = wlin[w]; rf[w] = Ar[NQ - 1 - w]; }

    float acc = 0.0f;
    #pragma unroll
    for (int k = 0; k < UN; k++) {
        u64 P = fma2(R[k], R[k], mul2(I[k], I[k]));   // packed |amp|^2
        float p0, p1;
        unpack2(P, p0, p1);
        unsigned y0 = (unsigned)warp | ((unsigned)lane << 5) | ((unsigned)k << 10);
        unsigned y1 = y0 | (1u << 13);
        float z0 = 0.0f, z1 = 0.0f;
        #pragma unroll
        for (int w = 0; w < NQ; w++) {
            z0 += ((__popc(rf[w] & y0) & 1) ? -wl[w] : wl[w]);
            z1 += ((__popc(rf[w] & y1) & 1) ? -wl[w] : wl[w]);
        }
        acc += p0 * z0 + p1 * z1;
    }
    #pragma unroll
    for (int off = 16; off; off >>= 1)
        acc += __shfl_down_sync(0xffffffffu, acc, off);
    if (lane == 0) red[warp] = acc;
    __syncthreads();
    if (t == 0) {
        float tot = 0.0f;
        #pragma unroll
        for (int q = 0; q < TPB / 32; q++) tot += red[q];
        out[b] = tot + blin[0];
    }
}

extern "C" void kernel_launch(void* const* d_in, const int* in_sizes, int n_in,
                              void* d_out, int out_size)
{
    // Bind inputs by element count (robust to metadata ordering):
    //   x: 128*14 = 1792, q_weights: 3*14*3 = 126, w_lin: 14, b_lin: 1
    const float* x    = nullptr;
    const float* qw   = nullptr;
    const float* wlin = nullptr;
    const float* blin = nullptr;
    for (int i = 0; i < n_in; i++) {
        switch (in_sizes[i]) {
            case 1792: x    = (const float*)d_in[i]; break;
            case 126:  qw   = (const float*)d_in[i]; break;
            case 14:   wlin = (const float*)d_in[i]; break;
            case 1:    blin = (const float*)d_in[i]; break;
            default: break;
        }
    }
    float* out = (float*)d_out;                  // (128, 1)

    cudaFuncSetAttribute(qsim_kernel,
                         cudaFuncAttributeMaxDynamicSharedMemorySize,
                         SMEM_BYTES);

    qsim_kernel<<<128, TPB, SMEM_BYTES>>>(x, qw, wlin, blin, out);
}